// round 14
// baseline (speedup 1.0000x reference)
#include <cuda_runtime.h>
#include <cstdint>
#include <math.h>

#define FULL_MASK 0xFFFFFFFFu

constexpr int   N_COLS  = 32768;
constexpr int   TPB     = 256;
constexpr int   F4PT    = N_COLS / 4 / TPB;  // 32 float4-batches per thread
constexpr int   KTOP    = 64;
constexpr int   NWARP   = TPB / 32;          // 8
constexpr int   PCAP    = 10;                // private slots/thread (lambda~0.91)
constexpr int   CAP     = 1024;              // compacted candidate capacity
constexpr int   CB      = 10;                // cached batches (40 KB SMEM row cache)
constexpr float THRESH  = 2.45f;             // E[count >= T] ~ 234 per N(0,1) row

// dynamic smem layout: [cache | priv strips | cand]
constexpr int   SM_CACHE_B = CB * TPB * 16;          // 40960
constexpr int   SM_PRIV_B  = TPB * PCAP * 4;         // 10240
constexpr int   SM_CAND_B  = CAP * 4;                //  4096
constexpr int   SMEM_DYN   = SM_CACHE_B + SM_PRIV_B + SM_CAND_B;   // 55296

__device__ __forceinline__ unsigned f2k(float f) {
    unsigned u = __float_as_uint(f);
    return (u & 0x80000000u) ? ~u : (u | 0x80000000u);
}
__device__ __forceinline__ float k2f(unsigned k) {
    unsigned u = (k & 0x80000000u) ? (k & 0x7FFFFFFFu) : ~k;
    return __uint_as_float(u);
}
// Exact fixed-point encode: v*2^32 is an exponent shift (exact); truncation exact.
__device__ __forceinline__ long long fixp(float v) {
    return (long long)(v * 4294967296.0f);
}

__global__ __launch_bounds__(TPB, 4)
void remaxkv_kernel(const float* __restrict__ x, float* __restrict__ out) {
    const int row  = blockIdx.x;
    const int tid  = threadIdx.x;
    const int lane = tid & 31;
    const int warp = tid >> 5;

    const float4* xr   = reinterpret_cast<const float4*>(x   + (size_t)row * N_COLS);
    float4*       outr = reinterpret_cast<float4*>      (out + (size_t)row * N_COLS);

    extern __shared__ char smem_dyn[];
    float4* s_cache = reinterpret_cast<float4*>(smem_dyn);
    float*  s_priv  = reinterpret_cast<float*>(smem_dyn + SM_CACHE_B);
    float*  s_cand  = reinterpret_cast<float*>(smem_dyn + SM_CACHE_B + SM_PRIV_B);

    __shared__ float     s_msum[NWARP];
    __shared__ int       s_wtot[NWARP];
    __shared__ int       s_woff[NWARP];
    __shared__ int       s_wovf[NWARP];
    __shared__ long long s_acc[NWARP];
    __shared__ int       s_cnt[NWARP];
    __shared__ int       s_nc, s_fb, s_tot;
    __shared__ float     s_kth, s_mag, s_ratio;

    // ===== Pass 1: stream row; relu-sum + private-strip capture + SMEM cache ====
    // Policy split: batches < CB (SMEM-cached, never re-read) -> .cs;
    // batches >= CB (re-read in pass 2) -> .cg.
    float ms  = 0.f;
    int   cnt = 0;
#pragma unroll
    for (int ii = 0; ii < F4PT; ii += 8) {
        float4 t[8];
#pragma unroll
        for (int u = 0; u < 8; u++) {
            t[u] = (ii + u < CB) ? __ldcs(xr + (ii + u) * TPB + tid)
                                 : __ldcg(xr + (ii + u) * TPB + tid);
        }
#pragma unroll
        for (int u = 0; u < 8; u++) {
            float4 v = t[u];
            if (ii + u < CB) s_cache[(ii + u) * TPB + tid] = v;   // compile-time pred
            ms += fmaxf(v.x, 0.f) + fmaxf(v.y, 0.f) + fmaxf(v.z, 0.f) + fmaxf(v.w, 0.f);
            float m4 = fmaxf(fmaxf(v.x, v.y), fmaxf(v.z, v.w));
            if (m4 >= THRESH) {   // rare per-thread branch (~2.8% of float4s)
                float c[4] = {v.x, v.y, v.z, v.w};
#pragma unroll
                for (int q = 0; q < 4; q++) {
                    if (c[q] >= THRESH) {
                        if (cnt < PCAP) s_priv[tid * PCAP + cnt] = c[q];
                        cnt++;
                    }
                }
            }
        }
    }
#pragma unroll
    for (int o = 16; o; o >>= 1) ms += __shfl_xor_sync(FULL_MASK, ms, o);

    // warp inclusive scan of stored counts (deterministic layout)
    int stored = cnt < PCAP ? cnt : PCAP;
    int sc = stored;
#pragma unroll
    for (int o = 1; o < 32; o <<= 1) {
        int t2 = __shfl_up_sync(FULL_MASK, sc, o);
        if (lane >= o) sc += t2;
    }
    int inwarp_off = sc - stored;
    int ov = __any_sync(FULL_MASK, cnt > PCAP) ? 1 : 0;
    if (lane == 31) { s_wtot[warp] = sc; s_wovf[warp] = ov; }
    if (lane == 0)  s_msum[warp] = ms;
    __syncthreads();

    // ===== Warp 0: mag total + cross-warp offsets + fallback decision ===========
    if (warp == 0) {
        float m = (lane < NWARP) ? s_msum[lane] : 0.f;
#pragma unroll
        for (int o = 16; o; o >>= 1) m += __shfl_xor_sync(FULL_MASK, m, o);
        int c  = (lane < NWARP) ? s_wtot[lane] : 0;
        int o2 = (lane < NWARP) ? s_wovf[lane] : 0;
        unsigned anyov = __ballot_sync(FULL_MASK, o2 != 0);
        int s2 = c;
#pragma unroll
        for (int o = 1; o < 32; o <<= 1) {
            int t2 = __shfl_up_sync(FULL_MASK, s2, o);
            if (lane >= o) s2 += t2;
        }
        if (lane < NWARP) s_woff[lane] = s2 - c;
        int total = __shfl_sync(FULL_MASK, s2, NWARP - 1);
        if (lane == 0) {
            s_mag = m;
            s_nc  = total;
            s_fb  = (anyov != 0 || total < KTOP || total > CAP) ? 1 : 0;
        }
    }
    __syncthreads();

    if (!s_fb) {
        // ===== compact private strips into contiguous array ======================
        {
            int base = s_woff[warp] + inwarp_off;
            for (int i = 0; i < stored; i++) s_cand[base + i] = s_priv[tid * PCAP + i];
        }
        __syncthreads();
        const int nc = s_nc;

        // ===== O(nc^2) parallel rank select: exact K-th value ===================
        for (int m = tid; m < nc; m += TPB) {
            float myv = s_cand[m];
            int cg = 0, te = 0;
            for (int j = 0; j < nc; j++) {   // broadcast LDS, conflict-free
                float v = s_cand[j];
                cg += (v > myv);
                te += (v == myv);
            }
            if (cg < KTOP && cg + te >= KTOP) s_kth = myv;   // benign same-value race
        }
        __syncthreads();
        const float kth = s_kth;

        // ===== exact top-K sum (int64 fixed point => order-independent) =========
        long long acc = 0; int cgt = 0;
        for (int m = tid; m < nc; m += TPB) {
            float v = s_cand[m];
            if (v > kth) { acc += fixp(v); cgt++; }
        }
#pragma unroll
        for (int o = 16; o; o >>= 1) acc += __shfl_xor_sync(FULL_MASK, acc, o);
        cgt = __reduce_add_sync(FULL_MASK, cgt);
        if (lane == 0) { s_acc[warp] = acc; s_cnt[warp] = cgt; }
        __syncthreads();
        if (warp == 0) {
            long long a = (lane < NWARP) ? s_acc[lane] : 0;
            int      cc = (lane < NWARP) ? s_cnt[lane] : 0;
#pragma unroll
            for (int o = 16; o; o >>= 1) a += __shfl_xor_sync(FULL_MASK, a, o);
            cc = __reduce_add_sync(FULL_MASK, cc);
            if (lane == 0) {
                double magk = (double)a * (1.0 / 4294967296.0)
                            + (double)(KTOP - cc) * (double)kth;
                float r = (float)(magk / (double)s_mag);
                if (!isfinite(r)) r = 0.f;
                s_ratio = r;
            }
        }
        __syncthreads();
    } else {
        // ===== generic fallback: exact block bisection over gmem (cold) =========
        unsigned lo = 0u, hi = 0xFFFFFFFFu;
        while (hi - lo > 1u) {
            unsigned mid = lo + ((hi - lo) >> 1);
            int c = 0;
            for (int i = tid; i < N_COLS / 4; i += TPB) {
                float4 v = __ldcg(xr + i);
                c += (f2k(v.x) >= mid) + (f2k(v.y) >= mid) + (f2k(v.z) >= mid) + (f2k(v.w) >= mid);
            }
            c = __reduce_add_sync(FULL_MASK, c);
            if (lane == 0) s_cnt[warp] = c;
            __syncthreads();
            if (warp == 0) {
                int cc = (lane < NWARP) ? s_cnt[lane] : 0;
                cc = __reduce_add_sync(FULL_MASK, cc);
                if (lane == 0) s_tot = cc;
            }
            __syncthreads();
            if (s_tot >= KTOP) lo = mid; else hi = mid;
            __syncthreads();
        }
        long long acc = 0; int cg = 0;
        for (int i = tid; i < N_COLS / 4; i += TPB) {
            float4 v = __ldcg(xr + i);
            if (f2k(v.x) > lo) { acc += fixp(v.x); cg++; }
            if (f2k(v.y) > lo) { acc += fixp(v.y); cg++; }
            if (f2k(v.z) > lo) { acc += fixp(v.z); cg++; }
            if (f2k(v.w) > lo) { acc += fixp(v.w); cg++; }
        }
#pragma unroll
        for (int o = 16; o; o >>= 1) acc += __shfl_xor_sync(FULL_MASK, acc, o);
        cg = __reduce_add_sync(FULL_MASK, cg);
        if (lane == 0) { s_acc[warp] = acc; s_cnt[warp] = cg; }
        __syncthreads();
        if (warp == 0) {
            long long a = (lane < NWARP) ? s_acc[lane] : 0;
            int      cc = (lane < NWARP) ? s_cnt[lane] : 0;
#pragma unroll
            for (int o = 16; o; o >>= 1) a += __shfl_xor_sync(FULL_MASK, a, o);
            cc = __reduce_add_sync(FULL_MASK, cc);
            if (lane == 0) {
                double magk = (double)a * (1.0 / 4294967296.0)
                            + (double)(KTOP - cc) * (double)k2f(lo);
                float r = (float)(magk / (double)s_mag);
                if (!isfinite(r)) r = 0.f;
                s_ratio = r;
            }
        }
        __syncthreads();
    }

    const float r = s_ratio;

    // ===== Pass 2a: gmem batches 10..31, REVERSE order (freshest L2 first) ======
    // Coverage: ii = 24 covers 24..31, ii = 16 covers 16..23, then 10..15 (6-chunk);
    // SMEM covers 0..9. Each batch exactly once.
#pragma unroll
    for (int ii = F4PT - 8; ii >= 16; ii -= 8) {
        float4 t[8];
#pragma unroll
        for (int u = 0; u < 8; u++) t[u] = __ldcs(xr + (ii + u) * TPB + tid);
#pragma unroll
        for (int u = 0; u < 8; u++) {
            float4 v = t[u], o;
            o.x = fmaxf(v.x, 0.f) * r;
            o.y = fmaxf(v.y, 0.f) * r;
            o.z = fmaxf(v.z, 0.f) * r;
            o.w = fmaxf(v.w, 0.f) * r;
            __stcs(outr + (ii + u) * TPB + tid, o);
        }
    }
    {
        float4 t[6];
#pragma unroll
        for (int u = 0; u < 6; u++) t[u] = __ldcs(xr + (CB + u) * TPB + tid);
#pragma unroll
        for (int u = 0; u < 6; u++) {
            float4 v = t[u], o;
            o.x = fmaxf(v.x, 0.f) * r;
            o.y = fmaxf(v.y, 0.f) * r;
            o.z = fmaxf(v.z, 0.f) * r;
            o.w = fmaxf(v.w, 0.f) * r;
            __stcs(outr + (CB + u) * TPB + tid, o);
        }
    }

    // ===== Pass 2b: SMEM-cached batches 0..CB-1 (no L2/DRAM traffic) ============
#pragma unroll
    for (int u = 0; u < CB; u++) {
        float4 v = s_cache[u * TPB + tid], o;
        o.x = fmaxf(v.x, 0.f) * r;
        o.y = fmaxf(v.y, 0.f) * r;
        o.z = fmaxf(v.z, 0.f) * r;
        o.w = fmaxf(v.w, 0.f) * r;
        __stcs(outr + u * TPB + tid, o);
    }
}

extern "C" void kernel_launch(void* const* d_in, const int* in_sizes, int n_in,
                              void* d_out, int out_size) {
    const float* x  = (const float*)d_in[0];
    float*      out = (float*)d_out;
    int n    = in_sizes[0];
    int rows = n / N_COLS;
    // Deterministic host-side attribute set (no allocation; capture-safe).
    cudaFuncSetAttribute(remaxkv_kernel,
                         cudaFuncAttributeMaxDynamicSharedMemorySize, SMEM_DYN);
    remaxkv_kernel<<<rows, TPB, SMEM_DYN>>>(x, out);
}

// round 17
// speedup vs baseline: 1.2071x; 1.2071x over previous
#include <cuda_runtime.h>
#include <cstdint>
#include <math.h>

#define FULL_MASK 0xFFFFFFFFu

constexpr int   N_COLS  = 32768;
constexpr int   TPB     = 256;
constexpr int   F4PT    = N_COLS / 4 / TPB;  // 32 float4-batches per thread
constexpr int   KTOP    = 64;
constexpr int   NWARP   = TPB / 32;          // 8
constexpr int   PCAP    = 10;                // private slots/thread (lambda~0.6 now)
constexpr int   CAP     = 1024;              // compacted candidate capacity
constexpr int   CB      = 8;                 // cached batches (32 KB SMEM row cache)
constexpr float THRESH  = 2.6f;              // E[count >= T] ~ 153 per N(0,1) row

__device__ __forceinline__ unsigned f2k(float f) {
    unsigned u = __float_as_uint(f);
    return (u & 0x80000000u) ? ~u : (u | 0x80000000u);
}
__device__ __forceinline__ float k2f(unsigned k) {
    unsigned u = (k & 0x80000000u) ? (k & 0x7FFFFFFFu) : ~k;
    return __uint_as_float(u);
}
// Exact fixed-point encode: v*2^32 is an exponent shift (exact); truncation exact.
__device__ __forceinline__ long long fixp(float v) {
    return (long long)(v * 4294967296.0f);
}

__global__ __launch_bounds__(TPB, 4)
void remaxkv_kernel(const float* __restrict__ x, float* __restrict__ out) {
    const int row  = blockIdx.x;
    const int tid  = threadIdx.x;
    const int lane = tid & 31;
    const int warp = tid >> 5;

    const float4* xr   = reinterpret_cast<const float4*>(x   + (size_t)row * N_COLS);
    float4*       outr = reinterpret_cast<float4*>      (out + (size_t)row * N_COLS);

    __shared__ float4    s_cache[CB * TPB];      // 32 KB: batches 0..CB-1
    __shared__ float     s_priv[TPB * PCAP];     // 10 KB private candidate strips
    __shared__ float     s_cand[CAP];            //  4 KB compacted candidates
    __shared__ float     s_msum[NWARP];
    __shared__ int       s_wtot[NWARP];
    __shared__ int       s_woff[NWARP];
    __shared__ int       s_wovf[NWARP];
    __shared__ long long s_acc[NWARP];
    __shared__ int       s_cnt[NWARP];
    __shared__ int       s_nc, s_fb, s_tot;
    __shared__ float     s_kth, s_mag, s_ratio;

    // ===== Pass 1: stream row; relu-sum + private-strip capture + SMEM cache ====
    // Policy split: batches < CB (SMEM-cached, never re-read) -> .cs;
    // batches >= CB (re-read in pass 2) -> .cg.
    float ms  = 0.f;
    int   cnt = 0;
#pragma unroll
    for (int ii = 0; ii < F4PT; ii += 8) {
        float4 t[8];
#pragma unroll
        for (int u = 0; u < 8; u++) {
            t[u] = (ii + u < CB) ? __ldcs(xr + (ii + u) * TPB + tid)
                                 : __ldcg(xr + (ii + u) * TPB + tid);
        }
#pragma unroll
        for (int u = 0; u < 8; u++) {
            float4 v = t[u];
            if (ii + u < CB) s_cache[(ii + u) * TPB + tid] = v;   // compile-time pred
            ms += fmaxf(v.x, 0.f) + fmaxf(v.y, 0.f) + fmaxf(v.z, 0.f) + fmaxf(v.w, 0.f);
            float m4 = fmaxf(fmaxf(v.x, v.y), fmaxf(v.z, v.w));
            if (m4 >= THRESH) {   // rare per-thread branch (~1.8% of float4s)
                float c[4] = {v.x, v.y, v.z, v.w};
#pragma unroll
                for (int q = 0; q < 4; q++) {
                    if (c[q] >= THRESH) {
                        if (cnt < PCAP) s_priv[tid * PCAP + cnt] = c[q];
                        cnt++;
                    }
                }
            }
        }
    }
#pragma unroll
    for (int o = 16; o; o >>= 1) ms += __shfl_xor_sync(FULL_MASK, ms, o);

    // warp inclusive scan of stored counts (deterministic layout)
    int stored = cnt < PCAP ? cnt : PCAP;
    int sc = stored;
#pragma unroll
    for (int o = 1; o < 32; o <<= 1) {
        int t2 = __shfl_up_sync(FULL_MASK, sc, o);
        if (lane >= o) sc += t2;
    }
    int inwarp_off = sc - stored;
    int ov = __any_sync(FULL_MASK, cnt > PCAP) ? 1 : 0;
    if (lane == 31) { s_wtot[warp] = sc; s_wovf[warp] = ov; }
    if (lane == 0)  s_msum[warp] = ms;
    __syncthreads();

    // ===== Warp 0: mag total + cross-warp offsets + fallback decision ===========
    if (warp == 0) {
        float m = (lane < NWARP) ? s_msum[lane] : 0.f;
#pragma unroll
        for (int o = 16; o; o >>= 1) m += __shfl_xor_sync(FULL_MASK, m, o);
        int c  = (lane < NWARP) ? s_wtot[lane] : 0;
        int o2 = (lane < NWARP) ? s_wovf[lane] : 0;
        unsigned anyov = __ballot_sync(FULL_MASK, o2 != 0);
        int s2 = c;
#pragma unroll
        for (int o = 1; o < 32; o <<= 1) {
            int t2 = __shfl_up_sync(FULL_MASK, s2, o);
            if (lane >= o) s2 += t2;
        }
        if (lane < NWARP) s_woff[lane] = s2 - c;
        int total = __shfl_sync(FULL_MASK, s2, NWARP - 1);
        if (lane == 0) {
            s_mag = m;
            s_nc  = total;
            s_fb  = (anyov != 0 || total < KTOP || total > CAP) ? 1 : 0;
        }
    }
    __syncthreads();

    if (!s_fb) {
        // ===== compact private strips into contiguous array ======================
        {
            int base = s_woff[warp] + inwarp_off;
            for (int i = 0; i < stored; i++) s_cand[base + i] = s_priv[tid * PCAP + i];
        }
        __syncthreads();
        const int nc = s_nc;

        // ===== O(nc^2) parallel rank select: exact K-th value ===================
        for (int m = tid; m < nc; m += TPB) {
            float myv = s_cand[m];
            int cg = 0, te = 0;
            for (int j = 0; j < nc; j++) {   // broadcast LDS, conflict-free
                float v = s_cand[j];
                cg += (v > myv);
                te += (v == myv);
            }
            if (cg < KTOP && cg + te >= KTOP) s_kth = myv;   // benign same-value race
        }
        __syncthreads();
        const float kth = s_kth;

        // ===== exact top-K sum (int64 fixed point => order-independent) =========
        long long acc = 0; int cgt = 0;
        for (int m = tid; m < nc; m += TPB) {
            float v = s_cand[m];
            if (v > kth) { acc += fixp(v); cgt++; }
        }
#pragma unroll
        for (int o = 16; o; o >>= 1) acc += __shfl_xor_sync(FULL_MASK, acc, o);
        cgt = __reduce_add_sync(FULL_MASK, cgt);
        if (lane == 0) { s_acc[warp] = acc; s_cnt[warp] = cgt; }
        __syncthreads();
        if (warp == 0) {
            long long a = (lane < NWARP) ? s_acc[lane] : 0;
            int      cc = (lane < NWARP) ? s_cnt[lane] : 0;
#pragma unroll
            for (int o = 16; o; o >>= 1) a += __shfl_xor_sync(FULL_MASK, a, o);
            cc = __reduce_add_sync(FULL_MASK, cc);
            if (lane == 0) {
                double magk = (double)a * (1.0 / 4294967296.0)
                            + (double)(KTOP - cc) * (double)kth;
                float r = (float)(magk / (double)s_mag);
                if (!isfinite(r)) r = 0.f;
                s_ratio = r;
            }
        }
        __syncthreads();
    } else {
        // ===== generic fallback: exact block bisection over gmem (cold) =========
        unsigned lo = 0u, hi = 0xFFFFFFFFu;
        while (hi - lo > 1u) {
            unsigned mid = lo + ((hi - lo) >> 1);
            int c = 0;
            for (int i = tid; i < N_COLS / 4; i += TPB) {
                float4 v = __ldcg(xr + i);
                c += (f2k(v.x) >= mid) + (f2k(v.y) >= mid) + (f2k(v.z) >= mid) + (f2k(v.w) >= mid);
            }
            c = __reduce_add_sync(FULL_MASK, c);
            if (lane == 0) s_cnt[warp] = c;
            __syncthreads();
            if (warp == 0) {
                int cc = (lane < NWARP) ? s_cnt[lane] : 0;
                cc = __reduce_add_sync(FULL_MASK, cc);
                if (lane == 0) s_tot = cc;
            }
            __syncthreads();
            if (s_tot >= KTOP) lo = mid; else hi = mid;
            __syncthreads();
        }
        long long acc = 0; int cg = 0;
        for (int i = tid; i < N_COLS / 4; i += TPB) {
            float4 v = __ldcg(xr + i);
            if (f2k(v.x) > lo) { acc += fixp(v.x); cg++; }
            if (f2k(v.y) > lo) { acc += fixp(v.y); cg++; }
            if (f2k(v.z) > lo) { acc += fixp(v.z); cg++; }
            if (f2k(v.w) > lo) { acc += fixp(v.w); cg++; }
        }
#pragma unroll
        for (int o = 16; o; o >>= 1) acc += __shfl_xor_sync(FULL_MASK, acc, o);
        cg = __reduce_add_sync(FULL_MASK, cg);
        if (lane == 0) { s_acc[warp] = acc; s_cnt[warp] = cg; }
        __syncthreads();
        if (warp == 0) {
            long long a = (lane < NWARP) ? s_acc[lane] : 0;
            int      cc = (lane < NWARP) ? s_cnt[lane] : 0;
#pragma unroll
            for (int o = 16; o; o >>= 1) a += __shfl_xor_sync(FULL_MASK, a, o);
            cc = __reduce_add_sync(FULL_MASK, cc);
            if (lane == 0) {
                double magk = (double)a * (1.0 / 4294967296.0)
                            + (double)(KTOP - cc) * (double)k2f(lo);
                float r = (float)(magk / (double)s_mag);
                if (!isfinite(r)) r = 0.f;
                s_ratio = r;
            }
        }
        __syncthreads();
    }

    const float r = s_ratio;

    // ===== Pass 2a: gmem batches CB..31, REVERSE order (freshest L2 first) ======
    // ii = 24 covers 24..31, 16 covers 16..23, 8 covers 8..15; SMEM covers 0..7.
#pragma unroll
    for (int ii = F4PT - 8; ii >= CB; ii -= 8) {
        float4 t[8];
#pragma unroll
        for (int u = 0; u < 8; u++) t[u] = __ldcs(xr + (ii + u) * TPB + tid);
#pragma unroll
        for (int u = 0; u < 8; u++) {
            float4 v = t[u], o;
            o.x = fmaxf(v.x, 0.f) * r;
            o.y = fmaxf(v.y, 0.f) * r;
            o.z = fmaxf(v.z, 0.f) * r;
            o.w = fmaxf(v.w, 0.f) * r;
            __stcs(outr + (ii + u) * TPB + tid, o);
        }
    }

    // ===== Pass 2b: SMEM-cached batches 0..CB-1 (no L2/DRAM traffic) ============
#pragma unroll
    for (int u = 0; u < CB; u++) {
        float4 v = s_cache[u * TPB + tid], o;
        o.x = fmaxf(v.x, 0.f) * r;
        o.y = fmaxf(v.y, 0.f) * r;
        o.z = fmaxf(v.z, 0.f) * r;
        o.w = fmaxf(v.w, 0.f) * r;
        __stcs(outr + u * TPB + tid, o);
    }
}

extern "C" void kernel_launch(void* const* d_in, const int* in_sizes, int n_in,
                              void* d_out, int out_size) {
    const float* x  = (const float*)d_in[0];
    float*      out = (float*)d_out;
    int n    = in_sizes[0];
    int rows = n / N_COLS;
    remaxkv_kernel<<<rows, TPB>>>(x, out);
}